// round 14
// baseline (speedup 1.0000x reference)
#include <cuda_runtime.h>
#include <cuda_fp16.h>

// 3D LUT trilinear interpolation — round 14.
// R13 evidence: L1tex 80.9% binding, issue 62.7%; wavefront-count model closes.
// Remaining loss = LSU idle while each warp runs its FMA tree. This round
// software-pipelines the gather: LDG 2 iterations ahead, LDS 1 iteration
// ahead, FMA consumes the previous iteration's q registers. 2-pixel groups
// keep the double-buffered state under the 64-reg/1024-thread ceiling.
// Keep: half2 b-pair smem table, persistent 148-CTA single wave, channel =
// bid%3 L2 x-sharing, magic floor (no clamps: x strictly in [0,1)), __stcs.

#define LUT_D  33
#define LUT_D2 (33 * 33)
#define LUT_D3 (33 * 33 * 33)      // 35937
#define HW     (1024 * 1024)
#define NBATCH 8
#define NPIX   (NBATCH * HW)       // 8388608
#define NPAIR  (NPIX / 2)          // 4194304 float2 groups
#define NCTA   148
#define SMEM_BYTES (LUT_D3 * 4)    // 143748 B of half2 b-pairs

#define MAGIC 12582912.0f          // 2^23 + 2^22
#define MAGIC_I 0x4B400000

struct Px2 { float2 r, g, b; };

__device__ __forceinline__ Px2 load_x2(const float* __restrict__ x, int pairIdx)
{
    int p  = pairIdx << 1;
    int bi = p >> 20;
    int hw = p & (HW - 1);
    const float* xb0 = x + (size_t)(bi * 3) * HW + hw;
    Px2 v;
    v.r = *(const float2*)(xb0);
    v.g = *(const float2*)(xb0 + HW);
    v.b = *(const float2*)(xb0 + 2 * HW);
    return v;
}

// Address + fractional setup: fixed-lat ALU only, no clamps.
__device__ __forceinline__ void lut_setup(float r, float g, float b,
                                          int& base, float& fr, float& fg, float& fb)
{
    float tr = fmaf(r, 32.0f, -0.5f) + MAGIC;
    float tg = fmaf(g, 32.0f, -0.5f) + MAGIC;
    float tb = fmaf(b, 32.0f, -0.5f) + MAGIC;

    int ir = __float_as_int(tr) - MAGIC_I;
    int ig = __float_as_int(tg) - MAGIC_I;
    int ib = __float_as_int(tb) - MAGIC_I;

    fr = fmaf(r, 32.0f, -(tr - MAGIC));
    fg = fmaf(g, 32.0f, -(tg - MAGIC));
    fb = fmaf(b, 32.0f, -(tb - MAGIC));

    base = ir * LUT_D2 + ig * LUT_D + ib;
}

// State for one 2-pixel group: 8 gathered pairs + 6 fracs + bookkeeping.
struct Stage {
    half2 q00[2], q01[2], q10[2], q11[2];
    float fr[2], fg[2], fb[2];
};

__device__ __forceinline__ void gather(const half2* __restrict__ slut,
                                       const Px2& v, Stage& s)
{
    int base0, base1;
    lut_setup(v.r.x, v.g.x, v.b.x, base0, s.fr[0], s.fg[0], s.fb[0]);
    lut_setup(v.r.y, v.g.y, v.b.y, base1, s.fr[1], s.fg[1], s.fb[1]);

    s.q00[0] = slut[base0];
    s.q01[0] = slut[base0 + LUT_D];
    s.q10[0] = slut[base0 + LUT_D2];
    s.q11[0] = slut[base0 + LUT_D2 + LUT_D];
    s.q00[1] = slut[base1];
    s.q01[1] = slut[base1 + LUT_D];
    s.q10[1] = slut[base1 + LUT_D2];
    s.q11[1] = slut[base1 + LUT_D2 + LUT_D];
}

__device__ __forceinline__ float2 lerp2(const Stage& s)
{
    float o[2];
    #pragma unroll
    for (int k = 0; k < 2; k++) {
        float2 a00 = __half22float2(s.q00[k]);
        float2 a01 = __half22float2(s.q01[k]);
        float2 a10 = __half22float2(s.q10[k]);
        float2 a11 = __half22float2(s.q11[k]);

        float c00 = fmaf(s.fb[k], a00.y - a00.x, a00.x);
        float c01 = fmaf(s.fb[k], a01.y - a01.x, a01.x);
        float c10 = fmaf(s.fb[k], a10.y - a10.x, a10.x);
        float c11 = fmaf(s.fb[k], a11.y - a11.x, a11.x);

        float c0 = fmaf(s.fg[k], c01 - c00, c00);
        float c1 = fmaf(s.fg[k], c11 - c10, c10);
        o[k] = fmaf(s.fr[k], c1 - c0, c0);
    }
    return make_float2(o[0], o[1]);
}

__global__ __launch_bounds__(1024, 1)
void TrilinearInterpolation_82171314307385_kernel(const float* __restrict__ lut,
                                                  const float* __restrict__ x,
                                                  float* __restrict__ out)
{
    extern __shared__ half2 slut[];

    const int c  = blockIdx.x % 3;
    const int r  = blockIdx.x / 3;
    const int nc = (c == 0) ? 50 : 49;

    const float* lutc = lut + c * LUT_D3;
    for (int i = threadIdx.x; i < LUT_D3; i += blockDim.x) {
        float a0 = lutc[i];
        float a1 = lutc[min(i + 1, LUT_D3 - 1)];
        slut[i] = __floats2half2_rn(a0, a1);
    }
    __syncthreads();

    const int start = (int)(((long long)r * NPAIR) / nc);
    const int end   = (int)(((long long)(r + 1) * NPAIR) / nc);

    int i0 = start + (int)threadIdx.x;
    if (i0 >= end) return;

    // ---- pipeline prologue ----
    Px2 x0 = load_x2(x, i0);              // x for current group
    Stage sA;
    gather(slut, x0, sA);                 // LDS(i0) in flight

    int  i1 = i0 + 1024;
    bool v1 = (i1 < end);
    Px2  x1 = load_x2(x, v1 ? i1 : i0);   // LDG 1 ahead (clamped)

    while (true) {
        int  i2 = i1 + 1024;
        bool v2 = (i2 < end);
        Px2  x2 = load_x2(x, v2 ? i2 : i0);   // LDG 2 ahead

        // issue next group's LDS batch before consuming current q regs
        Stage sB;
        gather(slut, x1, sB);

        // consume current group
        float2 o = lerp2(sA);
        {
            int p  = i0 << 1;
            int bi = p >> 20;
            int hw = p & (HW - 1);
            __stcs((float2*)(out + (size_t)(bi * 3 + c) * HW + hw), o);
        }

        if (!v1) break;
        i0 = i1; sA = sB;
        i1 = i2; v1 = v2; x1 = x2;
    }
}

extern "C" void kernel_launch(void* const* d_in, const int* in_sizes, int n_in,
                              void* d_out, int out_size)
{
    const float* lut = (const float*)d_in[0];
    const float* x   = (const float*)d_in[1];
    float* out       = (float*)d_out;
    (void)in_sizes; (void)n_in; (void)out_size;

    cudaFuncSetAttribute(TrilinearInterpolation_82171314307385_kernel,
                         cudaFuncAttributeMaxDynamicSharedMemorySize, SMEM_BYTES);

    TrilinearInterpolation_82171314307385_kernel<<<NCTA, 1024, SMEM_BYTES>>>(lut, x, out);
}

// round 15
// speedup vs baseline: 1.0793x; 1.0793x over previous
#include <cuda_runtime.h>
#include <cuda_fp16.h>

// 3D LUT trilinear interpolation — round 15.
// R14 regressed (2-px pipeline: more instrs/px, L1 62%). Revert to R13 skeleton.
// New this round:
//  (a) grid = actual SM count (GB300 = 152 SMs per B300_MICROARCH, not 148) via
//      cudaDeviceGetAttribute -> no idle SMs, still exactly one wave.
//  (b) 8-px groups: two float4 sub-groups per iteration, processed with R13's
//      exact 4-px batched-gather code -> half the loop/branch overhead per px,
//      latency exposed once per 8 px, two independent LDS->lerp chains.
// Keep: half2 b-pair smem table, channel = bid%3 (L2 x-sharing), magic floor
// (no clamps; x strictly in [0,1)), __stcs output stores.

#define LUT_D  33
#define LUT_D2 (33 * 33)
#define LUT_D3 (33 * 33 * 33)      // 35937
#define HW     (1024 * 1024)
#define NBATCH 8
#define NPIX   (NBATCH * HW)       // 8388608
#define NG8    (NPIX / 8)          // 1048576 8-pixel groups
#define SMEM_BYTES (LUT_D3 * 4)    // 143748 B of half2 b-pairs

#define MAGIC 12582912.0f          // 2^23 + 2^22
#define MAGIC_I 0x4B400000

struct Px8 { float4 r0, r1, g0, g1, b0, b1; };

__device__ __forceinline__ Px8 load_x8(const float* __restrict__ x, int g8)
{
    int p  = g8 << 3;
    int bi = p >> 20;
    int hw = p & (HW - 1);
    const float* xb0 = x + (size_t)(bi * 3) * HW + hw;
    Px8 v;
    v.r0 = *(const float4*)(xb0);
    v.r1 = *(const float4*)(xb0 + 4);
    v.g0 = *(const float4*)(xb0 + HW);
    v.g1 = *(const float4*)(xb0 + HW + 4);
    v.b0 = *(const float4*)(xb0 + 2 * HW);
    v.b1 = *(const float4*)(xb0 + 2 * HW + 4);
    return v;
}

// Address + fractional setup: fixed-lat ALU only, no clamps (v strictly < 32).
__device__ __forceinline__ void lut_setup(float r, float g, float b,
                                          int& base, float& fr, float& fg, float& fb)
{
    float tr = fmaf(r, 32.0f, -0.5f) + MAGIC;   // rne -> floor encoding
    float tg = fmaf(g, 32.0f, -0.5f) + MAGIC;
    float tb = fmaf(b, 32.0f, -0.5f) + MAGIC;

    int ir = __float_as_int(tr) - MAGIC_I;
    int ig = __float_as_int(tg) - MAGIC_I;
    int ib = __float_as_int(tb) - MAGIC_I;

    fr = fmaf(r, 32.0f, -(tr - MAGIC));
    fg = fmaf(g, 32.0f, -(tg - MAGIC));
    fb = fmaf(b, 32.0f, -(tb - MAGIC));

    base = ir * LUT_D2 + ig * LUT_D + ib;
}

// R13's exact 4-px block: batched setup, 16 back-to-back LDS, fp32 lerp trees.
__device__ __forceinline__ float4 quad(const half2* __restrict__ slut,
                                       float4 xr, float4 xg, float4 xb)
{
    int   base[4];
    float fr[4], fg[4], fb[4];
    lut_setup(xr.x, xg.x, xb.x, base[0], fr[0], fg[0], fb[0]);
    lut_setup(xr.y, xg.y, xb.y, base[1], fr[1], fg[1], fb[1]);
    lut_setup(xr.z, xg.z, xb.z, base[2], fr[2], fg[2], fb[2]);
    lut_setup(xr.w, xg.w, xb.w, base[3], fr[3], fg[3], fb[3]);

    half2 q00[4], q01[4], q10[4], q11[4];
    #pragma unroll
    for (int k = 0; k < 4; k++) {
        q00[k] = slut[base[k]];
        q01[k] = slut[base[k] + LUT_D];
        q10[k] = slut[base[k] + LUT_D2];
        q11[k] = slut[base[k] + LUT_D2 + LUT_D];
    }

    float o[4];
    #pragma unroll
    for (int k = 0; k < 4; k++) {
        float2 a00 = __half22float2(q00[k]);
        float2 a01 = __half22float2(q01[k]);
        float2 a10 = __half22float2(q10[k]);
        float2 a11 = __half22float2(q11[k]);

        float c00 = fmaf(fb[k], a00.y - a00.x, a00.x);
        float c01 = fmaf(fb[k], a01.y - a01.x, a01.x);
        float c10 = fmaf(fb[k], a10.y - a10.x, a10.x);
        float c11 = fmaf(fb[k], a11.y - a11.x, a11.x);

        float c0 = fmaf(fg[k], c01 - c00, c00);
        float c1 = fmaf(fg[k], c11 - c10, c10);
        o[k] = fmaf(fr[k], c1 - c0, c0);
    }
    return make_float4(o[0], o[1], o[2], o[3]);
}

__global__ __launch_bounds__(1024, 1)
void TrilinearInterpolation_82171314307385_kernel(const float* __restrict__ lut,
                                                  const float* __restrict__ x,
                                                  float* __restrict__ out)
{
    extern __shared__ half2 slut[];

    const int c  = blockIdx.x % 3;
    const int r  = blockIdx.x / 3;
    const int nc = ((int)gridDim.x + 2 - c) / 3;   // CTAs serving this channel

    const float* lutc = lut + c * LUT_D3;
    for (int i = threadIdx.x; i < LUT_D3; i += blockDim.x) {
        float a0 = lutc[i];
        float a1 = lutc[min(i + 1, LUT_D3 - 1)];
        slut[i] = __floats2half2_rn(a0, a1);
    }
    __syncthreads();

    const int start = (int)(((long long)r * NG8) / nc);
    const int end   = (int)(((long long)(r + 1) * NG8) / nc);

    int idx = start + (int)threadIdx.x;
    if (idx >= end) return;

    Px8 cur = load_x8(x, idx);

    while (true) {
        int  nidx = idx + 1024;
        bool have_next = (nidx < end);
        Px8  nxt;
        if (have_next) nxt = load_x8(x, nidx);   // prefetch: 6 LDG.128, max MLP

        int p  = idx << 3;
        int bi = p >> 20;
        int hw = p & (HW - 1);
        float* op = out + (size_t)(bi * 3 + c) * HW + hw;

        float4 o0 = quad(slut, cur.r0, cur.g0, cur.b0);
        __stcs((float4*)(op), o0);
        float4 o1 = quad(slut, cur.r1, cur.g1, cur.b1);
        __stcs((float4*)(op + 4), o1);

        if (!have_next) break;
        idx = nidx;
        cur = nxt;
    }
}

extern "C" void kernel_launch(void* const* d_in, const int* in_sizes, int n_in,
                              void* d_out, int out_size)
{
    const float* lut = (const float*)d_in[0];
    const float* x   = (const float*)d_in[1];
    float* out       = (float*)d_out;
    (void)in_sizes; (void)n_in; (void)out_size;

    int nsm = 148;
    cudaDeviceGetAttribute(&nsm, cudaDevAttrMultiProcessorCount, 0);  // GB300: 152

    cudaFuncSetAttribute(TrilinearInterpolation_82171314307385_kernel,
                         cudaFuncAttributeMaxDynamicSharedMemorySize, SMEM_BYTES);

    TrilinearInterpolation_82171314307385_kernel<<<nsm, 1024, SMEM_BYTES>>>(lut, x, out);
}

// round 16
// speedup vs baseline: 1.2795x; 1.1856x over previous
#include <cuda_runtime.h>
#include <cuda_fp16.h>

// 3D LUT trilinear interpolation — round 16.
// R15 post-mortem: 8-px groups hit the 64-reg ceiling -> spills -> 79.9us.
// R14 (2-px) and R12 (fp16 tree) also regressed. R13 (67.7us) is the validated
// local optimum shape. This round = R13 verbatim + the one clean R15 win:
// grid = actual SM count (152 on GB300) so no SM idles, still one wave.
// Keep: half2 b-pair smem table (4 LDS.32/px-ch), channel = bid%3 for L2
// x-sharing, batched 16-LDS gather, 1-deep float4 prefetch, magic floor with
// no clamps (x strictly in [0,1) -> i0 <= 31, max tap 35935 < 35937), __stcs.

#define LUT_D  33
#define LUT_D2 (33 * 33)
#define LUT_D3 (33 * 33 * 33)      // 35937
#define HW     (1024 * 1024)
#define NBATCH 8
#define NPIX   (NBATCH * HW)       // 8388608
#define NGROUPS (NPIX / 4)         // 2097152 float4 groups
#define SMEM_BYTES (LUT_D3 * 4)    // 143748 B of half2 b-pairs

#define MAGIC 12582912.0f          // 2^23 + 2^22
#define MAGIC_I 0x4B400000

// Address + fractional setup: 5 fixed-lat ops per component, no converts,
// no clamps (v strictly < 32).
__device__ __forceinline__ void lut_setup(float r, float g, float b,
                                          int& base, float& fr, float& fg, float& fb)
{
    float tr = fmaf(r, 32.0f, -0.5f) + MAGIC;   // rne -> floor encoding
    float tg = fmaf(g, 32.0f, -0.5f) + MAGIC;
    float tb = fmaf(b, 32.0f, -0.5f) + MAGIC;

    int ir = __float_as_int(tr) - MAGIC_I;
    int ig = __float_as_int(tg) - MAGIC_I;
    int ib = __float_as_int(tb) - MAGIC_I;

    fr = fmaf(r, 32.0f, -(tr - MAGIC));
    fg = fmaf(g, 32.0f, -(tg - MAGIC));
    fb = fmaf(b, 32.0f, -(tb - MAGIC));

    base = ir * LUT_D2 + ig * LUT_D + ib;
}

__global__ __launch_bounds__(1024, 1)
void TrilinearInterpolation_82171314307385_kernel(const float* __restrict__ lut,
                                                  const float* __restrict__ x,
                                                  float* __restrict__ out)
{
    extern __shared__ half2 slut[];

    const int c  = blockIdx.x % 3;                  // channel
    const int r  = blockIdx.x / 3;                  // region within channel
    const int nc = ((int)gridDim.x + 2 - c) / 3;    // CTAs serving this channel

    // Stage this channel's LUT as half2 (c[i], c[i+1]) b-pairs. Once per run.
    const float* lutc = lut + c * LUT_D3;
    for (int i = threadIdx.x; i < LUT_D3; i += blockDim.x) {
        float a0 = lutc[i];
        float a1 = lutc[min(i + 1, LUT_D3 - 1)];
        slut[i] = __floats2half2_rn(a0, a1);
    }
    __syncthreads();

    // Proportional split of float4 groups across this channel's CTAs.
    const int start = (int)(((long long)r * NGROUPS) / nc);
    const int end   = (int)(((long long)(r + 1) * NGROUPS) / nc);

    int idx = start + (int)threadIdx.x;
    if (idx >= end) return;

    // prologue: first group
    int p  = idx << 2;
    int bi = p >> 20;
    int hw = p & (HW - 1);
    const float* xb0 = x + (size_t)(bi * 3) * HW + hw;
    float4 xr = *(const float4*)(xb0);
    float4 xg = *(const float4*)(xb0 + HW);
    float4 xb = *(const float4*)(xb0 + 2 * HW);

    while (true) {
        int nidx = idx + 1024;
        float4 nr, ng, nb;
        bool have_next = (nidx < end);
        if (have_next) {
            int np  = nidx << 2;
            int nbi = np >> 20;
            int nhw = np & (HW - 1);
            const float* nxb0 = x + (size_t)(nbi * 3) * HW + nhw;
            nr = *(const float4*)(nxb0);
            ng = *(const float4*)(nxb0 + HW);
            nb = *(const float4*)(nxb0 + 2 * HW);
        }

        // ---- phase 1: address math (fixed-lat only) ----
        int   base[4];
        float fr[4], fg[4], fb[4];
        lut_setup(xr.x, xg.x, xb.x, base[0], fr[0], fg[0], fb[0]);
        lut_setup(xr.y, xg.y, xb.y, base[1], fr[1], fg[1], fb[1]);
        lut_setup(xr.z, xg.z, xb.z, base[2], fr[2], fg[2], fb[2]);
        lut_setup(xr.w, xg.w, xb.w, base[3], fr[3], fg[3], fb[3]);

        // ---- phase 2: 16 LDS back-to-back ----
        half2 q00[4], q01[4], q10[4], q11[4];
        #pragma unroll
        for (int k = 0; k < 4; k++) {
            q00[k] = slut[base[k]];
            q01[k] = slut[base[k] + LUT_D];
            q10[k] = slut[base[k] + LUT_D2];
            q11[k] = slut[base[k] + LUT_D2 + LUT_D];
        }

        // ---- phase 3: fp32 lerp trees ----
        float o[4];
        #pragma unroll
        for (int k = 0; k < 4; k++) {
            float2 a00 = __half22float2(q00[k]);
            float2 a01 = __half22float2(q01[k]);
            float2 a10 = __half22float2(q10[k]);
            float2 a11 = __half22float2(q11[k]);

            float c00 = fmaf(fb[k], a00.y - a00.x, a00.x);
            float c01 = fmaf(fb[k], a01.y - a01.x, a01.x);
            float c10 = fmaf(fb[k], a10.y - a10.x, a10.x);
            float c11 = fmaf(fb[k], a11.y - a11.x, a11.x);

            float c0 = fmaf(fg[k], c01 - c00, c00);
            float c1 = fmaf(fg[k], c11 - c10, c10);
            o[k] = fmaf(fr[k], c1 - c0, c0);
        }

        // streaming store: keep output from evicting the shared x window in L2
        __stcs((float4*)(out + (size_t)(bi * 3 + c) * HW + hw),
               make_float4(o[0], o[1], o[2], o[3]));

        if (!have_next) break;
        idx = nidx;
        p  = idx << 2;
        bi = p >> 20;
        hw = p & (HW - 1);
        xr = nr; xg = ng; xb = nb;
    }
}

extern "C" void kernel_launch(void* const* d_in, const int* in_sizes, int n_in,
                              void* d_out, int out_size)
{
    const float* lut = (const float*)d_in[0];
    const float* x   = (const float*)d_in[1];
    float* out       = (float*)d_out;
    (void)in_sizes; (void)n_in; (void)out_size;

    int nsm = 148;
    cudaDeviceGetAttribute(&nsm, cudaDevAttrMultiProcessorCount, 0);  // GB300: 152

    cudaFuncSetAttribute(TrilinearInterpolation_82171314307385_kernel,
                         cudaFuncAttributeMaxDynamicSharedMemorySize, SMEM_BYTES);

    TrilinearInterpolation_82171314307385_kernel<<<nsm, 1024, SMEM_BYTES>>>(lut, x, out);
}

// round 17
// speedup vs baseline: 1.3024x; 1.0179x over previous
#include <cuda_runtime.h>
#include <cuda_fp16.h>

// 3D LUT trilinear interpolation — round 17.
// R16 (67.4us, L1 82.4%, regs 51) is the validated skeleton. Analysis this
// round killed: texture trilinear (8-bit weights -> ~5e-3 rel err), bf16 table
// (~1.7e-3), quad/hybrid smem tables (divergence cancels the LDS.64 win),
// cross-channel rebalancing (re-stage cost > 1.3us imbalance).
// Only change: unroll-2 with A/B register rotation -> removes 12 rotation MOVs
// and half the branches per 4-px group. Memory behavior identical.
// Keep: half2 b-pair smem table, grid = SM count (152), channel = bid%3 for
// L2 x-sharing, batched 16-LDS gather, 1-deep float4 prefetch, magic floor
// (no clamps: x strictly in [0,1)), __stcs output stores.

#define LUT_D  33
#define LUT_D2 (33 * 33)
#define LUT_D3 (33 * 33 * 33)      // 35937
#define HW     (1024 * 1024)
#define NBATCH 8
#define NPIX   (NBATCH * HW)       // 8388608
#define NGROUPS (NPIX / 4)         // 2097152 float4 groups
#define SMEM_BYTES (LUT_D3 * 4)    // 143748 B of half2 b-pairs

#define MAGIC 12582912.0f          // 2^23 + 2^22
#define MAGIC_I 0x4B400000

struct Px4 { float4 r, g, b; };

__device__ __forceinline__ Px4 load_x4(const float* __restrict__ x, int grp)
{
    int p  = grp << 2;
    int bi = p >> 20;
    int hw = p & (HW - 1);
    const float* xb0 = x + (size_t)(bi * 3) * HW + hw;
    Px4 v;
    v.r = *(const float4*)(xb0);
    v.g = *(const float4*)(xb0 + HW);
    v.b = *(const float4*)(xb0 + 2 * HW);
    return v;
}

// Address + fractional setup: fixed-lat ALU only, no converts, no clamps
// (v strictly < 32; max tap index 35935 < 35937).
__device__ __forceinline__ void lut_setup(float r, float g, float b,
                                          int& base, float& fr, float& fg, float& fb)
{
    float tr = fmaf(r, 32.0f, -0.5f) + MAGIC;   // rne -> floor encoding
    float tg = fmaf(g, 32.0f, -0.5f) + MAGIC;
    float tb = fmaf(b, 32.0f, -0.5f) + MAGIC;

    int ir = __float_as_int(tr) - MAGIC_I;
    int ig = __float_as_int(tg) - MAGIC_I;
    int ib = __float_as_int(tb) - MAGIC_I;

    fr = fmaf(r, 32.0f, -(tr - MAGIC));
    fg = fmaf(g, 32.0f, -(tg - MAGIC));
    fb = fmaf(b, 32.0f, -(tb - MAGIC));

    base = ir * LUT_D2 + ig * LUT_D + ib;
}

// Batched 4-px block: setup, 16 back-to-back LDS, fp32 lerp trees, stcs store.
__device__ __forceinline__ void process_store(const half2* __restrict__ slut,
                                              const Px4& v, int grp, int c,
                                              float* __restrict__ out)
{
    int   base[4];
    float fr[4], fg[4], fb[4];
    lut_setup(v.r.x, v.g.x, v.b.x, base[0], fr[0], fg[0], fb[0]);
    lut_setup(v.r.y, v.g.y, v.b.y, base[1], fr[1], fg[1], fb[1]);
    lut_setup(v.r.z, v.g.z, v.b.z, base[2], fr[2], fg[2], fb[2]);
    lut_setup(v.r.w, v.g.w, v.b.w, base[3], fr[3], fg[3], fb[3]);

    half2 q00[4], q01[4], q10[4], q11[4];
    #pragma unroll
    for (int k = 0; k < 4; k++) {
        q00[k] = slut[base[k]];
        q01[k] = slut[base[k] + LUT_D];
        q10[k] = slut[base[k] + LUT_D2];
        q11[k] = slut[base[k] + LUT_D2 + LUT_D];
    }

    float o[4];
    #pragma unroll
    for (int k = 0; k < 4; k++) {
        float2 a00 = __half22float2(q00[k]);
        float2 a01 = __half22float2(q01[k]);
        float2 a10 = __half22float2(q10[k]);
        float2 a11 = __half22float2(q11[k]);

        float c00 = fmaf(fb[k], a00.y - a00.x, a00.x);
        float c01 = fmaf(fb[k], a01.y - a01.x, a01.x);
        float c10 = fmaf(fb[k], a10.y - a10.x, a10.x);
        float c11 = fmaf(fb[k], a11.y - a11.x, a11.x);

        float c0 = fmaf(fg[k], c01 - c00, c00);
        float c1 = fmaf(fg[k], c11 - c10, c10);
        o[k] = fmaf(fr[k], c1 - c0, c0);
    }

    int p  = grp << 2;
    int bi = p >> 20;
    int hw = p & (HW - 1);
    __stcs((float4*)(out + (size_t)(bi * 3 + c) * HW + hw),
           make_float4(o[0], o[1], o[2], o[3]));
}

__global__ __launch_bounds__(1024, 1)
void TrilinearInterpolation_82171314307385_kernel(const float* __restrict__ lut,
                                                  const float* __restrict__ x,
                                                  float* __restrict__ out)
{
    extern __shared__ half2 slut[];

    const int c  = blockIdx.x % 3;                  // channel
    const int r  = blockIdx.x / 3;                  // region within channel
    const int nc = ((int)gridDim.x + 2 - c) / 3;    // CTAs serving this channel

    // Stage this channel's LUT as half2 (c[i], c[i+1]) b-pairs. Once per run.
    const float* lutc = lut + c * LUT_D3;
    for (int i = threadIdx.x; i < LUT_D3; i += blockDim.x) {
        float a0 = lutc[i];
        float a1 = lutc[min(i + 1, LUT_D3 - 1)];
        slut[i] = __floats2half2_rn(a0, a1);
    }
    __syncthreads();

    const int start = (int)(((long long)r * NGROUPS) / nc);
    const int end   = (int)(((long long)(r + 1) * NGROUPS) / nc);

    int idx = start + (int)threadIdx.x;
    if (idx >= end) return;

    // ---- unroll-2 main loop: A/B register sets, no rotation MOVs ----
    Px4 A = load_x4(x, idx);
    int idxB = idx + 1024;

    while (true) {
        bool haveB = (idxB < end);
        Px4 B;
        if (haveB) B = load_x4(x, idxB);            // prefetch while A computes

        process_store(slut, A, idx, c, out);
        if (!haveB) break;

        int  idxC  = idxB + 1024;
        bool haveC = (idxC < end);
        if (haveC) A = load_x4(x, idxC);            // prefetch into A's regs

        process_store(slut, B, idxB, c, out);
        if (!haveC) break;

        idx  = idxC;
        idxB = idxC + 1024;
    }
}

extern "C" void kernel_launch(void* const* d_in, const int* in_sizes, int n_in,
                              void* d_out, int out_size)
{
    const float* lut = (const float*)d_in[0];
    const float* x   = (const float*)d_in[1];
    float* out       = (float*)d_out;
    (void)in_sizes; (void)n_in; (void)out_size;

    int nsm = 148;
    cudaDeviceGetAttribute(&nsm, cudaDevAttrMultiProcessorCount, 0);  // GB300: 152

    cudaFuncSetAttribute(TrilinearInterpolation_82171314307385_kernel,
                         cudaFuncAttributeMaxDynamicSharedMemorySize, SMEM_BYTES);

    TrilinearInterpolation_82171314307385_kernel<<<nsm, 1024, SMEM_BYTES>>>(lut, x, out);
}